// round 15
// baseline (speedup 1.0000x reference)
#include <cuda_runtime.h>
#include <cuda_fp16.h>

#define NN 100000
#define EE 1600000
#define GG 64
#define NB ((NN + 255) / 256)   // 391 scan blocks
#define DB 64                   // degree buckets (clamped)

// ---------------- device scratch ----------------
__device__ alignas(16) __half2 g_hp0[NN * 4];    // 8 feats as 4 half2
__device__ alignas(16) __half2 g_hp1[NN * 8];    // 16 feats
__device__ alignas(16) __half2 g_hp2[NN * 16];   // 32 feats
__device__ float4 g_z[NN];          // per-node z = hp3 @ Wf (layer-3 epilogue)
__device__ int   g_csr[EE];
__device__ int   g_rowptr[NN];
__device__ int   g_cnt[NN];
__device__ int   g_deg[NN];         // in-degree WITHOUT self loop
__device__ float g_dinv[NN];
__device__ float2 g_db[NN];         // {dinv, bitcast(batch)}
__device__ int   g_bsum[NB];
__device__ float g_psum[GG * 4];
__device__ int   g_pcnt[GG];
__device__ float g_Wf[64 * 4];      // W4 @ Wlin
__device__ float g_bf[4];           // b4 @ Wlin + blin
__device__ int   g_dhist[DB];       // degree histogram
__device__ int   g_dhoff[DB];       // exclusive offsets
__device__ int   g_dcnt[DB];        // scatter cursors
__device__ int   g_perm[NN];        // nodes in degree-sorted order

__device__ __forceinline__ unsigned h2u(__half2 h) {
    return *reinterpret_cast<unsigned*>(&h);
}

// ---------------- init / degree ----------------
__global__ void k_zero() {
    int i = blockIdx.x * blockDim.x + threadIdx.x;
    if (i < NN) g_deg[i] = 0;
    if (i < GG * 4) g_psum[i] = 0.0f;
    if (i < GG) g_pcnt[i] = 0;
    if (i < DB) { g_dhist[i] = 0; g_dcnt[i] = 0; }
}
__global__ void k_deg_count(const int* __restrict__ dst) {
    int e = blockIdx.x * blockDim.x + threadIdx.x;
    if (e < EE) atomicAdd(&g_deg[dst[e]], 1);
}
// dinv + graph counts + fp16 prescaled layer-1 features + degree histogram + Wf
__global__ void k_dinv_prep(const int* __restrict__ batch, const float* __restrict__ x,
                            const float* __restrict__ W4, const float* __restrict__ b4,
                            const float* __restrict__ Wlin, const float* __restrict__ blin) {
    int n = blockIdx.x * blockDim.x + threadIdx.x;
    if (n < NN) {
        int dg = g_deg[n];
        float d = rsqrtf((float)(dg + 1));
        g_dinv[n] = d;
        int b = batch[n];
        g_db[n] = make_float2(d, __int_as_float(b));
        atomicAdd(&g_pcnt[b], 1);
        atomicAdd(&g_dhist[dg < DB ? dg : DB - 1], 1);
        float4 v0 = reinterpret_cast<const float4*>(x)[n * 2];
        float4 v1 = reinterpret_cast<const float4*>(x)[n * 2 + 1];
        __half2 h0 = __floats2half2_rn(v0.x * d, v0.y * d);
        __half2 h1 = __floats2half2_rn(v0.z * d, v0.w * d);
        __half2 h2 = __floats2half2_rn(v1.x * d, v1.y * d);
        __half2 h3 = __floats2half2_rn(v1.z * d, v1.w * d);
        uint4 pk = make_uint4(h2u(h0), h2u(h1), h2u(h2), h2u(h3));
        reinterpret_cast<uint4*>(g_hp0)[n] = pk;
    }
    if (blockIdx.x == 0) {
        int t = threadIdx.x;           // 256 = 64 rows x 4 cols
        int o = t >> 2, c = t & 3;
        float acc = 0.0f;
#pragma unroll 16
        for (int j = 0; j < 128; j++)
            acc += __ldg(&W4[o * 128 + j]) * __ldg(&Wlin[j * 4 + c]);
        g_Wf[o * 4 + c] = acc;
        if (t < 4) {
            float bb = blin[t];
            for (int j = 0; j < 128; j++) bb += b4[j] * __ldg(&Wlin[j * 4 + t]);
            g_bf[t] = bb;
        }
    }
}

// ---------------- scan: block-local exclusive + block sums ----------------
__global__ void k_scan1() {
    int t = threadIdx.x;
    int i = blockIdx.x * 256 + t;
    int v = (i < NN) ? g_deg[i] : 0;
    int lane = t & 31, w = t >> 5;
    int x = v;
#pragma unroll
    for (int d = 1; d < 32; d <<= 1) {
        int y = __shfl_up_sync(0xffffffffu, x, d);
        if (lane >= d) x += y;
    }
    __shared__ int ws[8];
    if (lane == 31) ws[w] = x;
    __syncthreads();
    if (w == 0) {
        int y = (lane < 8) ? ws[lane] : 0;
#pragma unroll
        for (int d = 1; d < 8; d <<= 1) {
            int z = __shfl_up_sync(0xffffffffu, y, d);
            if (lane >= d) y += z;
        }
        if (lane < 8) ws[lane] = y;
    }
    __syncthreads();
    int base = (w > 0) ? ws[w - 1] : 0;
    int incl = base + x;
    if (i < NN) {
        int ex = incl - v;
        g_rowptr[i] = ex;
        g_cnt[i] = ex;
    }
    if (t == 255) g_bsum[blockIdx.x] = incl;
}
// scan of block sums + 64-entry degree-bucket scan
__global__ void k_scan2() {
    int t = threadIdx.x;                       // 512 threads
    int v = (t < NB) ? g_bsum[t] : 0;
    int lane = t & 31, w = t >> 5;
    int x = v;
#pragma unroll
    for (int d = 1; d < 32; d <<= 1) {
        int y = __shfl_up_sync(0xffffffffu, x, d);
        if (lane >= d) x += y;
    }
    __shared__ int ws[16];
    __shared__ int dh[DB];
    if (t < DB) dh[t] = g_dhist[t];
    if (lane == 31) ws[w] = x;
    __syncthreads();
    if (w == 0) {
        int y = (lane < 16) ? ws[lane] : 0;
#pragma unroll
        for (int d = 1; d < 16; d <<= 1) {
            int z = __shfl_up_sync(0xffffffffu, y, d);
            if (lane >= d) y += z;
        }
        if (lane < 16) ws[lane] = y;
    }
    if (w == 1 && lane == 0) {      // serial 64-entry exclusive scan (cheap)
        int run = 0;
#pragma unroll
        for (int i = 0; i < DB; i++) {
            int h = dh[i];
            dh[i] = run;
            run += h;
        }
    }
    __syncthreads();
    int base = (w > 0) ? ws[w - 1] : 0;
    if (t < NB) g_bsum[t] = base + x - v;
    if (t < DB) g_dhoff[t] = dh[t];
}
// CSR fill + degree-sorted permutation scatter
__global__ void k_fill(const int* __restrict__ src, const int* __restrict__ dst) {
    int e = blockIdx.x * blockDim.x + threadIdx.x;
    if (e < EE) {
        int d = dst[e];
        int pos = atomicAdd(&g_cnt[d], 1) + __ldg(&g_bsum[d >> 8]);
        g_csr[pos] = src[e];
    }
    if (e < NN) {
        int dg = g_deg[e];
        int bk = dg < DB ? dg : DB - 1;
        int p = __ldg(&g_dhoff[bk]) + atomicAdd(&g_dcnt[bk], 1);
        g_perm[p] = e;
    }
}

// ---------------- fused layers 1-3 (degree-sorted, fp16 features) --------------
__device__ __forceinline__ const __half2* hp_in_of(int layer) {
    switch (layer) { case 1: return g_hp0; case 2: return g_hp1;
                     default: return g_hp2; }
}
__device__ __forceinline__ __half2* hp_out_of(int layer) {
    switch (layer) { case 1: return g_hp1; default: return g_hp2; }
}

template<int LYR, int FIN, int FOUT>
__global__ void __launch_bounds__(256)
k_layer(const float* __restrict__ W, const float* __restrict__ b,
        const float* __restrict__ aP)
{
    constexpr int L = FIN / 2;            // half2 lanes per node
    constexpr int NPW = 32 / L;           // nodes per warp
    constexpr bool ZOUT = (LYR == 3);
    static_assert(FOUT == 4 * L, "mapping assumes FOUT = 2*FIN");
    __shared__ alignas(16) float Ws[FIN * FOUT];
    __shared__ float bs[FOUT];
    __shared__ alignas(16) float Wfs[64 * 4];
    for (int i = threadIdx.x; i < FIN * FOUT; i += blockDim.x) Ws[i] = W[i];
    for (int i = threadIdx.x; i < FOUT; i += blockDim.x) bs[i] = b[i];
    if constexpr (ZOUT)
        for (int i = threadIdx.x; i < 256; i += blockDim.x) Wfs[i] = g_Wf[i];
    __syncthreads();
    float a = __ldg(aP);

    int warp = threadIdx.x >> 5, lane = threadIdx.x & 31;
    int sub = lane % L;
    int unit = (blockIdx.x * 8 + warp) * NPW + lane / L;
    if (unit >= NN) return;
    int node = __ldg(&g_perm[unit]);      // degree-sorted: sub-groups ~equal deg

    const __half2* __restrict__ hp = hp_in_of(LYR);
    float2 acc = __half22float2(__ldg(&hp[(size_t)node * L + sub]));  // self loop
    int e = __ldg(&g_rowptr[node]) + __ldg(&g_bsum[node >> 8]);
    int rem = __ldg(&g_deg[node]);
    for (; rem >= 8; rem -= 8, e += 8) {
        int s[8];
#pragma unroll
        for (int j = 0; j < 8; j++) s[j] = __ldg(g_csr + e + j);
        __half2 v[8];
#pragma unroll
        for (int j = 0; j < 8; j++) v[j] = __ldg(&hp[(size_t)s[j] * L + sub]);
        float sx = 0.f, sy = 0.f;
#pragma unroll
        for (int j = 0; j < 8; j++) {
            float2 f = __half22float2(v[j]);
            sx += f.x; sy += f.y;
        }
        acc.x += sx; acc.y += sy;
    }
    for (; rem >= 2; rem -= 2, e += 2) {
        int s0 = __ldg(g_csr + e), s1 = __ldg(g_csr + e + 1);
        float2 v0 = __half22float2(__ldg(&hp[(size_t)s0 * L + sub]));
        float2 v1 = __half22float2(__ldg(&hp[(size_t)s1 * L + sub]));
        acc.x += v0.x + v1.x; acc.y += v0.y + v1.y;
    }
    if (rem) {
        int s = __ldg(g_csr + e);
        float2 v = __half22float2(__ldg(&hp[(size_t)s * L + sub]));
        acc.x += v.x; acc.y += v.y;
    }
    float dv = __ldg(&g_dinv[node]);
    acc.x *= dv; acc.y *= dv;

    float r0 = bs[4 * sub], r1 = bs[4 * sub + 1];
    float r2 = bs[4 * sub + 2], r3 = bs[4 * sub + 3];
#pragma unroll
    for (int k2 = 0; k2 < L; k2++) {
        float hx = __shfl_sync(0xffffffffu, acc.x, k2, L);
        float hy = __shfl_sync(0xffffffffu, acc.y, k2, L);
        float4 wa = *reinterpret_cast<const float4*>(&Ws[(2 * k2) * FOUT + 4 * sub]);
        float4 wb = *reinterpret_cast<const float4*>(&Ws[(2 * k2 + 1) * FOUT + 4 * sub]);
        r0 += hx * wa.x + hy * wb.x;
        r1 += hx * wa.y + hy * wb.y;
        r2 += hx * wa.z + hy * wb.z;
        r3 += hx * wa.w + hy * wb.w;
    }
    r0 = (r0 >= 0.f) ? r0 : a * r0;
    r1 = (r1 >= 0.f) ? r1 : a * r1;
    r2 = (r2 >= 0.f) ? r2 : a * r2;
    r3 = (r3 >= 0.f) ? r3 : a * r3;

    if constexpr (ZOUT) {
        float4 w0 = *reinterpret_cast<const float4*>(&Wfs[(4 * sub + 0) * 4]);
        float4 w1 = *reinterpret_cast<const float4*>(&Wfs[(4 * sub + 1) * 4]);
        float4 w2 = *reinterpret_cast<const float4*>(&Wfs[(4 * sub + 2) * 4]);
        float4 w3 = *reinterpret_cast<const float4*>(&Wfs[(4 * sub + 3) * 4]);
        float pz0 = dv * (r0 * w0.x + r1 * w1.x + r2 * w2.x + r3 * w3.x);
        float pz1 = dv * (r0 * w0.y + r1 * w1.y + r2 * w2.y + r3 * w3.y);
        float pz2 = dv * (r0 * w0.z + r1 * w1.z + r2 * w2.z + r3 * w3.z);
        float pz3 = dv * (r0 * w0.w + r1 * w1.w + r2 * w2.w + r3 * w3.w);
#pragma unroll
        for (int off = 1; off < 16; off <<= 1) {
            pz0 += __shfl_xor_sync(0xffffffffu, pz0, off);
            pz1 += __shfl_xor_sync(0xffffffffu, pz1, off);
            pz2 += __shfl_xor_sync(0xffffffffu, pz2, off);
            pz3 += __shfl_xor_sync(0xffffffffu, pz3, off);
        }
        if (sub == 0) g_z[node] = make_float4(pz0, pz1, pz2, pz3);
    } else {
        __half2* hp_out = hp_out_of(LYR);
        __half2 o0 = __floats2half2_rn(r0 * dv, r1 * dv);
        __half2 o1 = __floats2half2_rn(r2 * dv, r3 * dv);
        uint2 pk = make_uint2(h2u(o0), h2u(o1));
        reinterpret_cast<uint2*>(hp_out)[(size_t)node * L + sub] = pk;
    }
}

// ---------------- pooled layer-4: edge-parallel over z (16 B per edge) ----------
#define PG 1184
__global__ void __launch_bounds__(256)
k_pool4(const int* __restrict__ src, const int* __restrict__ dst)
{
    __shared__ float acc[GG * 4];
    acc[threadIdx.x] = 0.0f;        // blockDim == 256 == GG*4
    __syncthreads();
    const long long T = (long long)EE + NN;
    for (long long t = (long long)blockIdx.x * blockDim.x + threadIdx.x;
         t < T; t += (long long)PG * 256) {
        int s, d;
        if (t < EE) { s = __ldg(src + t); d = __ldg(dst + t); }
        else        { s = d = (int)(t - EE); }
        float2 db = __ldg(&g_db[d]);
        float w = db.x;
        int g = __float_as_int(db.y);
        float4 z = __ldg(&g_z[s]);
        atomicAdd(&acc[g * 4 + 0], w * z.x);
        atomicAdd(&acc[g * 4 + 1], w * z.y);
        atomicAdd(&acc[g * 4 + 2], w * z.z);
        atomicAdd(&acc[g * 4 + 3], w * z.w);
    }
    __syncthreads();
    float v = acc[threadIdx.x];
    if (v != 0.0f) atomicAdd(&g_psum[threadIdx.x], v);
}

// ---------------- head ----------------
__global__ void k_final(float* __restrict__ out) {
    int t = threadIdx.x;            // 64 graphs x 4 classes
    int g = t >> 2;
    int cls = t & 3;
    float inv = 1.0f / fmaxf((float)g_pcnt[g], 1.0f);
    out[g * 4 + cls] = g_psum[g * 4 + cls] * inv + g_bf[cls];
}

// ---------------- launch ----------------
extern "C" void kernel_launch(void* const* d_in, const int* in_sizes, int n_in,
                              void* d_out, int out_size) {
    const float* x    = (const float*)d_in[0];
    const int*   es   = (const int*)d_in[1];
    const int*   ed   = (const int*)d_in[2];
    const int*   bt   = (const int*)d_in[3];
    const float* W1   = (const float*)d_in[4];
    const float* b1   = (const float*)d_in[5];
    const float* W2   = (const float*)d_in[6];
    const float* b2   = (const float*)d_in[7];
    const float* W3   = (const float*)d_in[8];
    const float* b3   = (const float*)d_in[9];
    const float* W4   = (const float*)d_in[10];
    const float* b4   = (const float*)d_in[11];
    const float* a1   = (const float*)d_in[12];
    const float* a2   = (const float*)d_in[13];
    const float* a3   = (const float*)d_in[14];
    const float* Wlin = (const float*)d_in[15];
    const float* blin = (const float*)d_in[16];

    const int B = 256;
    auto gr = [](long long n, int b) { return (unsigned)((n + b - 1) / b); };

    k_zero<<<gr(NN, B), B>>>();
    k_deg_count<<<gr(EE, B), B>>>(ed);
    k_dinv_prep<<<gr(NN, B), B>>>(bt, x, W4, b4, Wlin, blin);
    k_scan1<<<NB, 256>>>();
    k_scan2<<<1, 512>>>();
    k_fill<<<gr(EE, B), B>>>(es, ed);

    // layers 1-3: degree-sorted sub-warp mapping
    k_layer<1, 8, 16><<<gr(NN, 64), B>>>(W1, b1, a1);
    k_layer<2, 16, 32><<<gr(NN, 32), B>>>(W2, b2, a2);
    k_layer<3, 32, 64><<<gr(NN, 16), B>>>(W3, b3, a3);   // emits z directly

    // layer 4 + mean-pool numerator: edge-parallel on z
    k_pool4<<<PG, 256>>>(es, ed);

    k_final<<<1, 256>>>((float*)d_out);
}

// round 16
// speedup vs baseline: 1.3958x; 1.3958x over previous
#include <cuda_runtime.h>
#include <cuda_fp16.h>

#define NN 100000
#define EE 1600000
#define GG 64
#define NB ((NN + 255) / 256)   // 391 scan blocks

// ---------------- device scratch ----------------
__device__ alignas(16) __half2 g_hp0[NN * 4];    // 8 feats as 4 half2 (16 B rows)
__device__ alignas(16) __half2 g_hp1[NN * 8];    // 16 feats (32 B rows)
__device__ alignas(16) __half2 g_hp2[NN * 16];   // 32 feats (64 B rows)
__device__ float4 g_z[NN];          // per-node z = hp3 @ Wf (layer-3 epilogue)
__device__ int   g_csr[EE];
__device__ int   g_rowptr[NN];
__device__ int   g_cnt[NN];
__device__ int   g_deg[NN];         // in-degree WITHOUT self loop
__device__ float g_dinv[NN];
__device__ float2 g_db[NN];         // {dinv, bitcast(batch)}
__device__ int   g_bsum[NB];
__device__ float g_psum[GG * 4];
__device__ int   g_pcnt[GG];
__device__ float g_Wf[64 * 4];      // W4 @ Wlin
__device__ float g_bf[4];           // b4 @ Wlin + blin

__device__ __forceinline__ unsigned h2u(__half2 h) {
    return *reinterpret_cast<unsigned*>(&h);
}
__device__ __forceinline__ __half2 u2h(unsigned u) {
    return *reinterpret_cast<__half2*>(&u);
}

// ---------------- init / degree ----------------
__global__ void k_zero() {
    int i = blockIdx.x * blockDim.x + threadIdx.x;
    if (i < NN) g_deg[i] = 0;
    if (i < GG * 4) g_psum[i] = 0.0f;
    if (i < GG) g_pcnt[i] = 0;
}
__global__ void k_deg_count(const int* __restrict__ dst) {
    int e = blockIdx.x * blockDim.x + threadIdx.x;
    if (e < EE) atomicAdd(&g_deg[dst[e]], 1);
}
// dinv + graph counts + prescaled fp16 layer-1 features + fused head weights
__global__ void k_dinv_prep(const int* __restrict__ batch, const float* __restrict__ x,
                            const float* __restrict__ W4, const float* __restrict__ b4,
                            const float* __restrict__ Wlin, const float* __restrict__ blin) {
    int n = blockIdx.x * blockDim.x + threadIdx.x;
    if (n < NN) {
        float d = rsqrtf((float)(g_deg[n] + 1));
        g_dinv[n] = d;
        int b = batch[n];
        g_db[n] = make_float2(d, __int_as_float(b));
        atomicAdd(&g_pcnt[b], 1);
        float4 v0 = reinterpret_cast<const float4*>(x)[n * 2];
        float4 v1 = reinterpret_cast<const float4*>(x)[n * 2 + 1];
        __half2 h0 = __floats2half2_rn(v0.x * d, v0.y * d);
        __half2 h1 = __floats2half2_rn(v0.z * d, v0.w * d);
        __half2 h2 = __floats2half2_rn(v1.x * d, v1.y * d);
        __half2 h3 = __floats2half2_rn(v1.z * d, v1.w * d);
        uint4 pk = make_uint4(h2u(h0), h2u(h1), h2u(h2), h2u(h3));
        reinterpret_cast<uint4*>(g_hp0)[n] = pk;
    }
    if (blockIdx.x == 0) {
        int t = threadIdx.x;           // 256 = 64 rows x 4 cols
        int o = t >> 2, c = t & 3;
        float acc = 0.0f;
#pragma unroll 16
        for (int j = 0; j < 128; j++)
            acc += __ldg(&W4[o * 128 + j]) * __ldg(&Wlin[j * 4 + c]);
        g_Wf[o * 4 + c] = acc;
        if (t < 4) {
            float bb = blin[t];
            for (int j = 0; j < 128; j++) bb += b4[j] * __ldg(&Wlin[j * 4 + t]);
            g_bf[t] = bb;
        }
    }
}

// ---------------- scan: block-local exclusive + block sums ----------------
__global__ void k_scan1() {
    int t = threadIdx.x;
    int i = blockIdx.x * 256 + t;
    int v = (i < NN) ? g_deg[i] : 0;
    int lane = t & 31, w = t >> 5;
    int x = v;
#pragma unroll
    for (int d = 1; d < 32; d <<= 1) {
        int y = __shfl_up_sync(0xffffffffu, x, d);
        if (lane >= d) x += y;
    }
    __shared__ int ws[8];
    if (lane == 31) ws[w] = x;
    __syncthreads();
    if (w == 0) {
        int y = (lane < 8) ? ws[lane] : 0;
#pragma unroll
        for (int d = 1; d < 8; d <<= 1) {
            int z = __shfl_up_sync(0xffffffffu, y, d);
            if (lane >= d) y += z;
        }
        if (lane < 8) ws[lane] = y;
    }
    __syncthreads();
    int base = (w > 0) ? ws[w - 1] : 0;
    int incl = base + x;
    if (i < NN) {
        int ex = incl - v;
        g_rowptr[i] = ex;
        g_cnt[i] = ex;
    }
    if (t == 255) g_bsum[blockIdx.x] = incl;
}
__global__ void k_scan2() {
    int t = threadIdx.x;                       // 512 threads
    int v = (t < NB) ? g_bsum[t] : 0;
    int lane = t & 31, w = t >> 5;
    int x = v;
#pragma unroll
    for (int d = 1; d < 32; d <<= 1) {
        int y = __shfl_up_sync(0xffffffffu, x, d);
        if (lane >= d) x += y;
    }
    __shared__ int ws[16];
    if (lane == 31) ws[w] = x;
    __syncthreads();
    if (w == 0) {
        int y = (lane < 16) ? ws[lane] : 0;
#pragma unroll
        for (int d = 1; d < 16; d <<= 1) {
            int z = __shfl_up_sync(0xffffffffu, y, d);
            if (lane >= d) y += z;
        }
        if (lane < 16) ws[lane] = y;
    }
    __syncthreads();
    int base = (w > 0) ? ws[w - 1] : 0;
    if (t < NB) g_bsum[t] = base + x - v;
}
__global__ void k_fill(const int* __restrict__ src, const int* __restrict__ dst) {
    int e = blockIdx.x * blockDim.x + threadIdx.x;
    if (e < EE) {
        int d = dst[e];
        int pos = atomicAdd(&g_cnt[d], 1) + __ldg(&g_bsum[d >> 8]);
        g_csr[pos] = src[e];
    }
}

// ---------------- fused layers 1-3 (uint2 gathers = 4 feats/lane) --------------
__device__ __forceinline__ const uint2* hp_in_of(int layer) {
    switch (layer) { case 1: return reinterpret_cast<const uint2*>(g_hp0);
                     case 2: return reinterpret_cast<const uint2*>(g_hp1);
                     default: return reinterpret_cast<const uint2*>(g_hp2); }
}
__device__ __forceinline__ uint4* hp_out_of(int layer) {
    switch (layer) { case 1: return reinterpret_cast<uint4*>(g_hp1);
                     default: return reinterpret_cast<uint4*>(g_hp2); }
}
struct F4 { float f0, f1, f2, f3; };
__device__ __forceinline__ F4 cvt(uint2 u) {
    float2 a = __half22float2(u2h(u.x));
    float2 b = __half22float2(u2h(u.y));
    return {a.x, a.y, b.x, b.y};
}

template<int LYR, int FIN, int FOUT>
__global__ void __launch_bounds__(256)
k_layer(const float* __restrict__ W, const float* __restrict__ b,
        const float* __restrict__ aP)
{
    constexpr int L = FIN / 4;            // uint2 lanes per node (4 feats each)
    constexpr int NPW = 32 / L;           // nodes per warp
    constexpr bool ZOUT = (LYR == 3);
    static_assert(FOUT == 8 * L, "mapping assumes FOUT = 2*FIN");
    __shared__ alignas(16) float Ws[FIN * FOUT];
    __shared__ float bs[FOUT];
    __shared__ alignas(16) float Wfs[64 * 4];
    for (int i = threadIdx.x; i < FIN * FOUT; i += blockDim.x) Ws[i] = W[i];
    for (int i = threadIdx.x; i < FOUT; i += blockDim.x) bs[i] = b[i];
    if constexpr (ZOUT)
        for (int i = threadIdx.x; i < 256; i += blockDim.x) Wfs[i] = g_Wf[i];
    __syncthreads();
    float a = __ldg(aP);

    int warp = threadIdx.x >> 5, lane = threadIdx.x & 31;
    int sub = lane % L;
    int node = (blockIdx.x * 8 + warp) * NPW + lane / L;
    if (node >= NN) return;

    const uint2* __restrict__ hp = hp_in_of(LYR);
    F4 acc = cvt(__ldg(&hp[(size_t)node * L + sub]));   // self loop
    int e = __ldg(&g_rowptr[node]) + __ldg(&g_bsum[node >> 8]);
    int rem = __ldg(&g_deg[node]);
    for (; rem >= 8; rem -= 8, e += 8) {
        int s[8];
#pragma unroll
        for (int j = 0; j < 8; j++) s[j] = __ldg(g_csr + e + j);
        uint2 v[8];
#pragma unroll
        for (int j = 0; j < 8; j++) v[j] = __ldg(&hp[(size_t)s[j] * L + sub]);
        float s0 = 0.f, s1 = 0.f, s2 = 0.f, s3 = 0.f;
#pragma unroll
        for (int j = 0; j < 8; j++) {
            F4 f = cvt(v[j]);
            s0 += f.f0; s1 += f.f1; s2 += f.f2; s3 += f.f3;
        }
        acc.f0 += s0; acc.f1 += s1; acc.f2 += s2; acc.f3 += s3;
    }
    for (; rem >= 2; rem -= 2, e += 2) {
        int i0 = __ldg(g_csr + e), i1 = __ldg(g_csr + e + 1);
        F4 f0 = cvt(__ldg(&hp[(size_t)i0 * L + sub]));
        F4 f1 = cvt(__ldg(&hp[(size_t)i1 * L + sub]));
        acc.f0 += f0.f0 + f1.f0; acc.f1 += f0.f1 + f1.f1;
        acc.f2 += f0.f2 + f1.f2; acc.f3 += f0.f3 + f1.f3;
    }
    if (rem) {
        int i0 = __ldg(g_csr + e);
        F4 f = cvt(__ldg(&hp[(size_t)i0 * L + sub]));
        acc.f0 += f.f0; acc.f1 += f.f1; acc.f2 += f.f2; acc.f3 += f.f3;
    }
    float dv = __ldg(&g_dinv[node]);
    acc.f0 *= dv; acc.f1 *= dv; acc.f2 *= dv; acc.f3 *= dv;

    // matmul: each lane computes 8 outputs o = 8*sub .. 8*sub+7
    float r[8];
#pragma unroll
    for (int i = 0; i < 8; i++) r[i] = bs[8 * sub + i];
#pragma unroll
    for (int k2 = 0; k2 < L; k2++) {
        float h0 = __shfl_sync(0xffffffffu, acc.f0, k2, L);
        float h1 = __shfl_sync(0xffffffffu, acc.f1, k2, L);
        float h2 = __shfl_sync(0xffffffffu, acc.f2, k2, L);
        float h3 = __shfl_sync(0xffffffffu, acc.f3, k2, L);
        float hk[4] = {h0, h1, h2, h3};
#pragma unroll
        for (int kk = 0; kk < 4; kk++) {
            const float* wrow = &Ws[(4 * k2 + kk) * FOUT + 8 * sub];
            float4 wa = *reinterpret_cast<const float4*>(wrow);
            float4 wb = *reinterpret_cast<const float4*>(wrow + 4);
            float h = hk[kk];
            r[0] += h * wa.x; r[1] += h * wa.y; r[2] += h * wa.z; r[3] += h * wa.w;
            r[4] += h * wb.x; r[5] += h * wb.y; r[6] += h * wb.z; r[7] += h * wb.w;
        }
    }
#pragma unroll
    for (int i = 0; i < 8; i++) r[i] = (r[i] >= 0.f) ? r[i] : a * r[i];

    if constexpr (ZOUT) {
        float z0 = 0.f, z1 = 0.f, z2 = 0.f, z3 = 0.f;
#pragma unroll
        for (int i = 0; i < 8; i++) {
            float4 wf = *reinterpret_cast<const float4*>(&Wfs[(8 * sub + i) * 4]);
            z0 += r[i] * wf.x; z1 += r[i] * wf.y;
            z2 += r[i] * wf.z; z3 += r[i] * wf.w;
        }
        z0 *= dv; z1 *= dv; z2 *= dv; z3 *= dv;
#pragma unroll
        for (int off = 1; off < L; off <<= 1) {
            z0 += __shfl_xor_sync(0xffffffffu, z0, off);
            z1 += __shfl_xor_sync(0xffffffffu, z1, off);
            z2 += __shfl_xor_sync(0xffffffffu, z2, off);
            z3 += __shfl_xor_sync(0xffffffffu, z3, off);
        }
        if (sub == 0) g_z[node] = make_float4(z0, z1, z2, z3);
    } else {
        __half2 o0 = __floats2half2_rn(r[0] * dv, r[1] * dv);
        __half2 o1 = __floats2half2_rn(r[2] * dv, r[3] * dv);
        __half2 o2 = __floats2half2_rn(r[4] * dv, r[5] * dv);
        __half2 o3 = __floats2half2_rn(r[6] * dv, r[7] * dv);
        uint4 pk = make_uint4(h2u(o0), h2u(o1), h2u(o2), h2u(o3));
        hp_out_of(LYR)[(size_t)node * L + sub] = pk;
    }
}

// ---------------- pooled layer-4: edge-parallel over z (16 B per edge) ----------
#define PG 1184
__global__ void __launch_bounds__(256)
k_pool4(const int* __restrict__ src, const int* __restrict__ dst)
{
    __shared__ float acc[GG * 4];
    acc[threadIdx.x] = 0.0f;        // blockDim == 256 == GG*4
    __syncthreads();
    const long long T = (long long)EE + NN;
    for (long long t = (long long)blockIdx.x * blockDim.x + threadIdx.x;
         t < T; t += (long long)PG * 256) {
        int s, d;
        if (t < EE) { s = __ldg(src + t); d = __ldg(dst + t); }
        else        { s = d = (int)(t - EE); }
        float2 db = __ldg(&g_db[d]);
        float w = db.x;
        int g = __float_as_int(db.y);
        float4 z = __ldg(&g_z[s]);
        atomicAdd(&acc[g * 4 + 0], w * z.x);
        atomicAdd(&acc[g * 4 + 1], w * z.y);
        atomicAdd(&acc[g * 4 + 2], w * z.z);
        atomicAdd(&acc[g * 4 + 3], w * z.w);
    }
    __syncthreads();
    float v = acc[threadIdx.x];
    if (v != 0.0f) atomicAdd(&g_psum[threadIdx.x], v);
}

// ---------------- head ----------------
__global__ void k_final(float* __restrict__ out) {
    int t = threadIdx.x;            // 64 graphs x 4 classes
    int g = t >> 2;
    int cls = t & 3;
    float inv = 1.0f / fmaxf((float)g_pcnt[g], 1.0f);
    out[g * 4 + cls] = g_psum[g * 4 + cls] * inv + g_bf[cls];
}

// ---------------- launch ----------------
extern "C" void kernel_launch(void* const* d_in, const int* in_sizes, int n_in,
                              void* d_out, int out_size) {
    const float* x    = (const float*)d_in[0];
    const int*   es   = (const int*)d_in[1];
    const int*   ed   = (const int*)d_in[2];
    const int*   bt   = (const int*)d_in[3];
    const float* W1   = (const float*)d_in[4];
    const float* b1   = (const float*)d_in[5];
    const float* W2   = (const float*)d_in[6];
    const float* b2   = (const float*)d_in[7];
    const float* W3   = (const float*)d_in[8];
    const float* b3   = (const float*)d_in[9];
    const float* W4   = (const float*)d_in[10];
    const float* b4   = (const float*)d_in[11];
    const float* a1   = (const float*)d_in[12];
    const float* a2   = (const float*)d_in[13];
    const float* a3   = (const float*)d_in[14];
    const float* Wlin = (const float*)d_in[15];
    const float* blin = (const float*)d_in[16];

    const int B = 256;
    auto gr = [](long long n, int b) { return (unsigned)((n + b - 1) / b); };

    k_zero<<<gr(NN, B), B>>>();
    k_deg_count<<<gr(EE, B), B>>>(ed);
    k_dinv_prep<<<gr(NN, B), B>>>(bt, x, W4, b4, Wlin, blin);
    k_scan1<<<NB, 256>>>();
    k_scan2<<<1, 512>>>();
    k_fill<<<gr(EE, B), B>>>(es, ed);

    // layers 1-3: uint2 sub-warp mapping, nodes/block = 8 * (32/L)
    k_layer<1, 8, 16><<<gr(NN, 128), B>>>(W1, b1, a1);
    k_layer<2, 16, 32><<<gr(NN, 64), B>>>(W2, b2, a2);
    k_layer<3, 32, 64><<<gr(NN, 32), B>>>(W3, b3, a3);   // emits z directly

    // layer 4 + mean-pool numerator: edge-parallel on z
    k_pool4<<<PG, 256>>>(es, ed);

    k_final<<<1, 256>>>((float*)d_out);
}

// round 17
// speedup vs baseline: 1.5211x; 1.0898x over previous
#include <cuda_runtime.h>
#include <cuda_fp16.h>

#define NN 100000
#define EE 1600000
#define GG 64
#define NB ((NN + 255) / 256)   // 391 scan blocks
#define PG 1184

// ---------------- device scratch (zero-initialized at load; self-cleaned) ------
__device__ alignas(16) __half2 g_hp0[NN * 4];    // 8 feats as 4 half2
__device__ alignas(16) __half2 g_hp1[NN * 8];    // 16 feats
__device__ alignas(16) __half2 g_hp2[NN * 16];   // 32 feats
__device__ float4 g_z[NN];          // per-node z = hp3 @ Wf (layer-3 epilogue)
__device__ int   g_csr[EE];
__device__ int   g_rowptr[NN];
__device__ int   g_cnt[NN];
__device__ int   g_deg[NN];         // in-degree WITHOUT self loop (re-zeroed by k_pool4)
__device__ float g_dinv[NN];
__device__ float2 g_db[NN];         // {dinv, bitcast(batch)}
__device__ int   g_bsum[NB];
__device__ float g_psum[GG * 4];    // re-zeroed by k_final
__device__ int   g_pcnt[GG];        // re-zeroed by k_final
__device__ float g_Wf[64 * 4];      // W4 @ Wlin
__device__ float g_bf[4];           // b4 @ Wlin + blin

__device__ __forceinline__ unsigned h2u(__half2 h) {
    return *reinterpret_cast<unsigned*>(&h);
}

// ---------------- degree ----------------
__global__ void k_deg_count(const int* __restrict__ dst) {
    int e = blockIdx.x * blockDim.x + threadIdx.x;
    if (e < EE) atomicAdd(&g_deg[dst[e]], 1);
}
// dinv + graph counts + prescaled fp16 layer-1 features + fused head weights
__global__ void k_dinv_prep(const int* __restrict__ batch, const float* __restrict__ x,
                            const float* __restrict__ W4, const float* __restrict__ b4,
                            const float* __restrict__ Wlin, const float* __restrict__ blin) {
    int n = blockIdx.x * blockDim.x + threadIdx.x;
    if (n < NN) {
        float d = rsqrtf((float)(g_deg[n] + 1));
        g_dinv[n] = d;
        int b = batch[n];
        g_db[n] = make_float2(d, __int_as_float(b));
        atomicAdd(&g_pcnt[b], 1);
        float4 v0 = reinterpret_cast<const float4*>(x)[n * 2];
        float4 v1 = reinterpret_cast<const float4*>(x)[n * 2 + 1];
        __half2 h0 = __floats2half2_rn(v0.x * d, v0.y * d);
        __half2 h1 = __floats2half2_rn(v0.z * d, v0.w * d);
        __half2 h2 = __floats2half2_rn(v1.x * d, v1.y * d);
        __half2 h3 = __floats2half2_rn(v1.z * d, v1.w * d);
        uint4 pk = make_uint4(h2u(h0), h2u(h1), h2u(h2), h2u(h3));
        reinterpret_cast<uint4*>(g_hp0)[n] = pk;
    }
    if (blockIdx.x == 0) {
        int t = threadIdx.x;           // 256 = 64 rows x 4 cols
        int o = t >> 2, c = t & 3;
        float acc = 0.0f;
#pragma unroll 16
        for (int j = 0; j < 128; j++)
            acc += __ldg(&W4[o * 128 + j]) * __ldg(&Wlin[j * 4 + c]);
        g_Wf[o * 4 + c] = acc;
        if (t < 4) {
            float bb = blin[t];
            for (int j = 0; j < 128; j++) bb += b4[j] * __ldg(&Wlin[j * 4 + t]);
            g_bf[t] = bb;
        }
    }
}

// ---------------- scan: block-local exclusive + block sums ----------------
__global__ void k_scan1() {
    int t = threadIdx.x;
    int i = blockIdx.x * 256 + t;
    int v = (i < NN) ? g_deg[i] : 0;
    int lane = t & 31, w = t >> 5;
    int x = v;
#pragma unroll
    for (int d = 1; d < 32; d <<= 1) {
        int y = __shfl_up_sync(0xffffffffu, x, d);
        if (lane >= d) x += y;
    }
    __shared__ int ws[8];
    if (lane == 31) ws[w] = x;
    __syncthreads();
    if (w == 0) {
        int y = (lane < 8) ? ws[lane] : 0;
#pragma unroll
        for (int d = 1; d < 8; d <<= 1) {
            int z = __shfl_up_sync(0xffffffffu, y, d);
            if (lane >= d) y += z;
        }
        if (lane < 8) ws[lane] = y;
    }
    __syncthreads();
    int base = (w > 0) ? ws[w - 1] : 0;
    int incl = base + x;
    if (i < NN) {
        int ex = incl - v;
        g_rowptr[i] = ex;
        g_cnt[i] = ex;
    }
    if (t == 255) g_bsum[blockIdx.x] = incl;
}
__global__ void k_scan2() {
    int t = threadIdx.x;                       // 512 threads
    int v = (t < NB) ? g_bsum[t] : 0;
    int lane = t & 31, w = t >> 5;
    int x = v;
#pragma unroll
    for (int d = 1; d < 32; d <<= 1) {
        int y = __shfl_up_sync(0xffffffffu, x, d);
        if (lane >= d) x += y;
    }
    __shared__ int ws[16];
    if (lane == 31) ws[w] = x;
    __syncthreads();
    if (w == 0) {
        int y = (lane < 16) ? ws[lane] : 0;
#pragma unroll
        for (int d = 1; d < 16; d <<= 1) {
            int z = __shfl_up_sync(0xffffffffu, y, d);
            if (lane >= d) y += z;
        }
        if (lane < 16) ws[lane] = y;
    }
    __syncthreads();
    int base = (w > 0) ? ws[w - 1] : 0;
    if (t < NB) g_bsum[t] = base + x - v;
}
__global__ void k_fill(const int* __restrict__ src, const int* __restrict__ dst) {
    int e = blockIdx.x * blockDim.x + threadIdx.x;
    if (e < EE) {
        int d = dst[e];
        int pos = atomicAdd(&g_cnt[d], 1) + __ldg(&g_bsum[d >> 8]);
        g_csr[pos] = src[e];
    }
}

// ---------------- fused layers 1-3 (fp16 features, fp32 math) ----------------
__device__ __forceinline__ const __half2* hp_in_of(int layer) {
    switch (layer) { case 1: return g_hp0; case 2: return g_hp1;
                     default: return g_hp2; }
}
__device__ __forceinline__ __half2* hp_out_of(int layer) {
    switch (layer) { case 1: return g_hp1; default: return g_hp2; }
}

template<int LYR, int FIN, int FOUT>
__global__ void __launch_bounds__(256)
k_layer(const float* __restrict__ W, const float* __restrict__ b,
        const float* __restrict__ aP)
{
    constexpr int L = FIN / 2;            // half2 lanes per node
    constexpr int NPW = 32 / L;           // nodes per warp
    constexpr bool ZOUT = (LYR == 3);
    static_assert(FOUT == 4 * L, "mapping assumes FOUT = 2*FIN");
    __shared__ alignas(16) float Ws[FIN * FOUT];
    __shared__ float bs[FOUT];
    __shared__ alignas(16) float Wfs[64 * 4];
    for (int i = threadIdx.x; i < FIN * FOUT; i += blockDim.x) Ws[i] = W[i];
    for (int i = threadIdx.x; i < FOUT; i += blockDim.x) bs[i] = b[i];
    if constexpr (ZOUT)
        for (int i = threadIdx.x; i < 256; i += blockDim.x) Wfs[i] = g_Wf[i];
    __syncthreads();
    float a = __ldg(aP);

    int warp = threadIdx.x >> 5, lane = threadIdx.x & 31;
    int sub = lane % L;
    int node = (blockIdx.x * 8 + warp) * NPW + lane / L;
    if (node >= NN) return;

    const __half2* __restrict__ hp = hp_in_of(LYR);
    float2 acc = __half22float2(__ldg(&hp[(size_t)node * L + sub]));  // self loop
    int e = __ldg(&g_rowptr[node]) + __ldg(&g_bsum[node >> 8]);
    int rem = __ldg(&g_deg[node]);
    for (; rem >= 8; rem -= 8, e += 8) {
        int s[8];
#pragma unroll
        for (int j = 0; j < 8; j++) s[j] = __ldg(g_csr + e + j);
        __half2 v[8];
#pragma unroll
        for (int j = 0; j < 8; j++) v[j] = __ldg(&hp[(size_t)s[j] * L + sub]);
        float sx = 0.f, sy = 0.f;
#pragma unroll
        for (int j = 0; j < 8; j++) {
            float2 f = __half22float2(v[j]);
            sx += f.x; sy += f.y;
        }
        acc.x += sx; acc.y += sy;
    }
    for (; rem >= 2; rem -= 2, e += 2) {
        int s0 = __ldg(g_csr + e), s1 = __ldg(g_csr + e + 1);
        float2 v0 = __half22float2(__ldg(&hp[(size_t)s0 * L + sub]));
        float2 v1 = __half22float2(__ldg(&hp[(size_t)s1 * L + sub]));
        acc.x += v0.x + v1.x; acc.y += v0.y + v1.y;
    }
    if (rem) {
        int s = __ldg(g_csr + e);
        float2 v = __half22float2(__ldg(&hp[(size_t)s * L + sub]));
        acc.x += v.x; acc.y += v.y;
    }
    float dv = __ldg(&g_dinv[node]);
    acc.x *= dv; acc.y *= dv;

    float r0 = bs[4 * sub], r1 = bs[4 * sub + 1];
    float r2 = bs[4 * sub + 2], r3 = bs[4 * sub + 3];
#pragma unroll
    for (int k2 = 0; k2 < L; k2++) {
        float hx = __shfl_sync(0xffffffffu, acc.x, k2, L);
        float hy = __shfl_sync(0xffffffffu, acc.y, k2, L);
        float4 wa = *reinterpret_cast<const float4*>(&Ws[(2 * k2) * FOUT + 4 * sub]);
        float4 wb = *reinterpret_cast<const float4*>(&Ws[(2 * k2 + 1) * FOUT + 4 * sub]);
        r0 += hx * wa.x + hy * wb.x;
        r1 += hx * wa.y + hy * wb.y;
        r2 += hx * wa.z + hy * wb.z;
        r3 += hx * wa.w + hy * wb.w;
    }
    r0 = (r0 >= 0.f) ? r0 : a * r0;
    r1 = (r1 >= 0.f) ? r1 : a * r1;
    r2 = (r2 >= 0.f) ? r2 : a * r2;
    r3 = (r3 >= 0.f) ? r3 : a * r3;

    if constexpr (ZOUT) {
        float4 w0 = *reinterpret_cast<const float4*>(&Wfs[(4 * sub + 0) * 4]);
        float4 w1 = *reinterpret_cast<const float4*>(&Wfs[(4 * sub + 1) * 4]);
        float4 w2 = *reinterpret_cast<const float4*>(&Wfs[(4 * sub + 2) * 4]);
        float4 w3 = *reinterpret_cast<const float4*>(&Wfs[(4 * sub + 3) * 4]);
        float pz0 = dv * (r0 * w0.x + r1 * w1.x + r2 * w2.x + r3 * w3.x);
        float pz1 = dv * (r0 * w0.y + r1 * w1.y + r2 * w2.y + r3 * w3.y);
        float pz2 = dv * (r0 * w0.z + r1 * w1.z + r2 * w2.z + r3 * w3.z);
        float pz3 = dv * (r0 * w0.w + r1 * w1.w + r2 * w2.w + r3 * w3.w);
#pragma unroll
        for (int off = 1; off < 16; off <<= 1) {
            pz0 += __shfl_xor_sync(0xffffffffu, pz0, off);
            pz1 += __shfl_xor_sync(0xffffffffu, pz1, off);
            pz2 += __shfl_xor_sync(0xffffffffu, pz2, off);
            pz3 += __shfl_xor_sync(0xffffffffu, pz3, off);
        }
        if (sub == 0) g_z[node] = make_float4(pz0, pz1, pz2, pz3);
    } else {
        __half2* hp_out = hp_out_of(LYR);
        __half2 o0 = __floats2half2_rn(r0 * dv, r1 * dv);
        __half2 o1 = __floats2half2_rn(r2 * dv, r3 * dv);
        uint2 pk = make_uint2(h2u(o0), h2u(o1));
        reinterpret_cast<uint2*>(hp_out)[(size_t)node * L + sub] = pk;
    }
}

// ---------------- pooled layer-4 + re-zero g_deg for next invocation -----------
__global__ void __launch_bounds__(256)
k_pool4(const int* __restrict__ src, const int* __restrict__ dst)
{
    __shared__ float acc[GG * 4];
    acc[threadIdx.x] = 0.0f;        // blockDim == 256 == GG*4
    __syncthreads();
    int gtid = blockIdx.x * blockDim.x + threadIdx.x;
    // self-clean: g_deg no longer needed this call; zero it for the next one
    for (int i = gtid; i < NN; i += PG * 256) g_deg[i] = 0;

    const long long T = (long long)EE + NN;
    for (long long t = gtid; t < T; t += (long long)PG * 256) {
        int s, d;
        if (t < EE) { s = __ldg(src + t); d = __ldg(dst + t); }
        else        { s = d = (int)(t - EE); }
        float2 db = __ldg(&g_db[d]);
        float w = db.x;
        int g = __float_as_int(db.y);
        float4 z = __ldg(&g_z[s]);
        atomicAdd(&acc[g * 4 + 0], w * z.x);
        atomicAdd(&acc[g * 4 + 1], w * z.y);
        atomicAdd(&acc[g * 4 + 2], w * z.z);
        atomicAdd(&acc[g * 4 + 3], w * z.w);
    }
    __syncthreads();
    float v = acc[threadIdx.x];
    if (v != 0.0f) atomicAdd(&g_psum[threadIdx.x], v);
}

// ---------------- head (+ re-zero psum/pcnt for next invocation) ---------------
__global__ void k_final(float* __restrict__ out) {
    int t = threadIdx.x;            // 64 graphs x 4 classes
    int g = t >> 2;
    int cls = t & 3;
    float inv = 1.0f / fmaxf((float)g_pcnt[g], 1.0f);
    out[g * 4 + cls] = g_psum[t] * inv + g_bf[cls];
    __syncthreads();                // all reads done before resetting
    g_psum[t] = 0.0f;
    if (t < GG) g_pcnt[t] = 0;
}

// ---------------- launch ----------------
extern "C" void kernel_launch(void* const* d_in, const int* in_sizes, int n_in,
                              void* d_out, int out_size) {
    const float* x    = (const float*)d_in[0];
    const int*   es   = (const int*)d_in[1];
    const int*   ed   = (const int*)d_in[2];
    const int*   bt   = (const int*)d_in[3];
    const float* W1   = (const float*)d_in[4];
    const float* b1   = (const float*)d_in[5];
    const float* W2   = (const float*)d_in[6];
    const float* b2   = (const float*)d_in[7];
    const float* W3   = (const float*)d_in[8];
    const float* b3   = (const float*)d_in[9];
    const float* W4   = (const float*)d_in[10];
    const float* b4   = (const float*)d_in[11];
    const float* a1   = (const float*)d_in[12];
    const float* a2   = (const float*)d_in[13];
    const float* a3   = (const float*)d_in[14];
    const float* Wlin = (const float*)d_in[15];
    const float* blin = (const float*)d_in[16];

    const int B = 256;
    auto gr = [](long long n, int b) { return (unsigned)((n + b - 1) / b); };

    // no k_zero: buffers are zero at load and self-cleaned each call
    k_deg_count<<<gr(EE, B), B>>>(ed);
    k_dinv_prep<<<gr(NN, B), B>>>(bt, x, W4, b4, Wlin, blin);
    k_scan1<<<NB, 256>>>();
    k_scan2<<<1, 512>>>();
    k_fill<<<gr(EE, B), B>>>(es, ed);

    // layers 1-3: sub-warp mapping, nodes/block = 8 * (32/L)
    k_layer<1, 8, 16><<<gr(NN, 64), B>>>(W1, b1, a1);
    k_layer<2, 16, 32><<<gr(NN, 32), B>>>(W2, b2, a2);
    k_layer<3, 32, 64><<<gr(NN, 16), B>>>(W3, b3, a3);   // emits z directly

    // layer 4 + mean-pool numerator: edge-parallel on z (also re-zeros g_deg)
    k_pool4<<<PG, 256>>>(es, ed);

    k_final<<<1, 256>>>((float*)d_out);
}